// round 1
// baseline (speedup 1.0000x reference)
#include <cuda_runtime.h>
#include <cuda_bf16.h>
#include <math.h>

// Problem constants
static constexpr int NN   = 32000;     // nodes
static constexpr int NB   = 16;        // graphs
static constexpr int NPG  = 2000;      // nodes per graph
static constexpr int KK   = 1600;      // clusters total
static constexpr int KPG  = 100;       // clusters per graph
static constexpr int DD   = 128;       // feature dim
static constexpr int EE   = 512000;    // edges
static constexpr int ADJ_ELEMS = KK * KK;        // 2,560,000
static constexpr int HP_ELEMS  = KK * DD;        // 204,800

// ---------------- scratch (__device__ globals; no allocations allowed) ------
__device__ float g_agg[(size_t)NN * DD];
__device__ float g_deg[NN];
__device__ float g_x[(size_t)NN * DD];
__device__ float g_t1[(size_t)NN * DD];
__device__ float g_feat[(size_t)NN * DD];
__device__ float g_x2[(size_t)NN * KK];          // 204.8 MB
__device__ float g_logits[(size_t)NN * KPG];
__device__ float g_assign[(size_t)NN * KPG];
__device__ float g_tmp[(size_t)NN * KPG];

// ---------------- zero ------------------------------------------------------
__global__ void zero_kernel(float* __restrict__ p, size_t n) {
    size_t i = (size_t)blockIdx.x * blockDim.x + threadIdx.x;
    size_t stride = (size_t)gridDim.x * blockDim.x;
    for (; i < n; i += stride) p[i] = 0.f;
}

// ---------------- edge aggregation: agg[dst] += h[src]; deg[dst] += 1 -------
__global__ void edge_agg_kernel(const float* __restrict__ h,
                                const int* __restrict__ src,
                                const int* __restrict__ dst) {
    int warp = (blockIdx.x * blockDim.x + threadIdx.x) >> 5;
    int lane = threadIdx.x & 31;
    if (warp >= EE) return;
    int s = src[warp];
    int d = dst[warp];
    const float* hr = h + (size_t)s * DD;
    float* ar = g_agg + (size_t)d * DD;
    atomicAdd(&ar[lane +  0], hr[lane +  0]);
    atomicAdd(&ar[lane + 32], hr[lane + 32]);
    atomicAdd(&ar[lane + 64], hr[lane + 64]);
    atomicAdd(&ar[lane + 96], hr[lane + 96]);
    if (lane == 0) atomicAdd(&g_deg[d], 1.0f);
}

// ---------------- x = h + agg / max(deg,1) ----------------------------------
__global__ void build_x_kernel(const float* __restrict__ h) {
    size_t i = (size_t)blockIdx.x * blockDim.x + threadIdx.x;
    if (i >= (size_t)NN * DD) return;
    int node = (int)(i >> 7);
    float dg = fmaxf(g_deg[node], 1.0f);
    g_x[i] = h[i] + g_agg[i] / dg;
}

// ---------------- generic tiled SGEMM (+bias +relu) -------------------------
// C[M,N] = relu(A[M,K] @ B[K,N] + bias)
// 128x128 block tile, 256 threads, 8x8 per thread, BK=8.
// z dimension: A += z*zsA, B += z*zsB (element offset), C += z*zsC, bias += z*zsBias
__global__ __launch_bounds__(256)
void sgemm_kernel(const float* __restrict__ A, const float* __restrict__ B,
                  const float* __restrict__ bias, float* __restrict__ C,
                  int M, int N, int K, int lda, int ldb, int ldc,
                  long zsA, long zsB, long zsC, long zsBias) {
    A    += (size_t)blockIdx.z * zsA;
    B    += (size_t)blockIdx.z * zsB;
    C    += (size_t)blockIdx.z * zsC;
    bias += (size_t)blockIdx.z * zsBias;

    __shared__ float As[8][128];
    __shared__ float Bs[8][128];

    const int tid = threadIdx.x;
    const int bm = blockIdx.x * 128;
    const int bn = blockIdx.y * 128;
    const int tx = tid & 15;
    const int ty = tid >> 4;
    const int rowBase = ty * 8;
    const int colBase = tx * 8;

    const int aRow = tid >> 1;           // 0..127
    const int aK   = (tid & 1) * 4;      // 0 or 4
    const int bK   = tid >> 5;           // 0..7
    const int bCol = (tid & 31) * 4;

    float acc[8][8];
#pragma unroll
    for (int i = 0; i < 8; i++)
#pragma unroll
        for (int j = 0; j < 8; j++) acc[i][j] = 0.f;

    for (int k0 = 0; k0 < K; k0 += 8) {
        // A tile (128 x 8), K guaranteed multiple of 8 and 16B-aligned rows
        {
            int r = bm + aRow;
            float4 v = make_float4(0.f, 0.f, 0.f, 0.f);
            if (r < M) v = *(const float4*)(A + (size_t)r * lda + (k0 + aK));
            As[aK + 0][aRow] = v.x;
            As[aK + 1][aRow] = v.y;
            As[aK + 2][aRow] = v.z;
            As[aK + 3][aRow] = v.w;
        }
        // B tile (8 x 128) with column guards (N may be 100)
        {
            const float* bp = B + (size_t)(k0 + bK) * ldb;
            int c = bn + bCol;
            Bs[bK][bCol + 0] = (c + 0 < N) ? bp[c + 0] : 0.f;
            Bs[bK][bCol + 1] = (c + 1 < N) ? bp[c + 1] : 0.f;
            Bs[bK][bCol + 2] = (c + 2 < N) ? bp[c + 2] : 0.f;
            Bs[bK][bCol + 3] = (c + 3 < N) ? bp[c + 3] : 0.f;
        }
        __syncthreads();
#pragma unroll
        for (int k = 0; k < 8; k++) {
            float a[8], b[8];
#pragma unroll
            for (int i = 0; i < 8; i++) a[i] = As[k][rowBase + i];
#pragma unroll
            for (int j = 0; j < 8; j++) b[j] = Bs[k][colBase + j];
#pragma unroll
            for (int i = 0; i < 8; i++)
#pragma unroll
                for (int j = 0; j < 8; j++) acc[i][j] += a[i] * b[j];
        }
        __syncthreads();
    }

#pragma unroll
    for (int i = 0; i < 8; i++) {
        int r = bm + rowBase + i;
        if (r >= M) continue;
#pragma unroll
        for (int j = 0; j < 8; j++) {
            int c = bn + colBase + j;
            if (c >= N) continue;
            float v = acc[i][j] + bias[c];
            C[(size_t)r * ldc + c] = fmaxf(v, 0.f);
        }
    }
}

// ---------------- per-node softmax over 100 compact logits ------------------
__global__ void softmax_kernel() {
    int node = (blockIdx.x * blockDim.x + threadIdx.x) >> 5;
    int lane = threadIdx.x & 31;
    if (node >= NN) return;
    const float* lp = g_logits + (size_t)node * KPG;
    float v[4];
    float mx = -1e30f;
#pragma unroll
    for (int i = 0; i < 4; i++) {
        int c = lane + 32 * i;
        v[i] = (c < KPG) ? lp[c] : -1e30f;
        mx = fmaxf(mx, v[i]);
    }
#pragma unroll
    for (int o = 16; o; o >>= 1) mx = fmaxf(mx, __shfl_xor_sync(0xFFFFFFFFu, mx, o));
    float sum = 0.f;
#pragma unroll
    for (int i = 0; i < 4; i++) {
        int c = lane + 32 * i;
        v[i] = (c < KPG) ? expf(v[i] - mx) : 0.f;
        sum += v[i];
    }
#pragma unroll
    for (int o = 16; o; o >>= 1) sum += __shfl_xor_sync(0xFFFFFFFFu, sum, o);
    float inv = 1.f / sum;
    float* ap = g_assign + (size_t)node * KPG;
#pragma unroll
    for (int i = 0; i < 4; i++) {
        int c = lane + 32 * i;
        if (c < KPG) ap[c] = v[i] * inv;
    }
}

// ---------------- tmp[dst] += assign[src]  (compact 100-wide rows) ----------
__global__ void edge_tmp_kernel(const int* __restrict__ src,
                                const int* __restrict__ dst) {
    int warp = (blockIdx.x * blockDim.x + threadIdx.x) >> 5;
    int lane = threadIdx.x & 31;
    if (warp >= EE) return;
    int s = src[warp];
    int d = dst[warp];
    const float* ap = g_assign + (size_t)s * KPG;
    float* tp = g_tmp + (size_t)d * KPG;
    atomicAdd(&tp[lane +  0], ap[lane +  0]);
    atomicAdd(&tp[lane + 32], ap[lane + 32]);
    atomicAdd(&tp[lane + 64], ap[lane + 64]);
    if (lane < 4) atomicAdd(&tp[lane + 96], ap[lane + 96]);
}

// ---------------- h_pool: per graph, assign_b^T [2000x100] @ feat_b [2000x128]
// split-K with atomic accumulation into d_out (pre-zeroed)
__global__ __launch_bounds__(256)
void hpool_kernel(float* __restrict__ out) {   // out = d_out + ADJ_ELEMS
    const int g = blockIdx.y;
    const int split = blockIdx.x;      // 8 splits
    const int kbeg = split * (NPG / 8);
    const int kend = kbeg + (NPG / 8);
    const float* A = g_assign + (size_t)g * NPG * KPG;
    const float* F = g_feat + (size_t)g * NPG * DD;

    __shared__ float As[8][KPG];
    __shared__ float Fs[8][DD];
    const int tx = threadIdx.x & 15;
    const int ty = threadIdx.x >> 4;

    float acc[7][8];
#pragma unroll
    for (int i = 0; i < 7; i++)
#pragma unroll
        for (int j = 0; j < 8; j++) acc[i][j] = 0.f;

    for (int k0 = kbeg; k0 < kend; k0 += 8) {
        int kc = min(8, kend - k0);
        for (int idx = threadIdx.x; idx < 8 * KPG; idx += 256) {
            int r = idx / KPG, c = idx % KPG;
            As[r][c] = (r < kc) ? A[(size_t)(k0 + r) * KPG + c] : 0.f;
        }
        for (int idx = threadIdx.x; idx < 8 * DD; idx += 256) {
            int r = idx >> 7, c = idx & 127;
            Fs[r][c] = (r < kc) ? F[(size_t)(k0 + r) * DD + c] : 0.f;
        }
        __syncthreads();
#pragma unroll
        for (int k = 0; k < 8; k++) {
            float a[7], f[8];
#pragma unroll
            for (int i = 0; i < 7; i++) {
                int c = ty + 16 * i;
                a[i] = (c < KPG) ? As[k][c] : 0.f;
            }
#pragma unroll
            for (int j = 0; j < 8; j++) f[j] = Fs[k][tx + 16 * j];
#pragma unroll
            for (int i = 0; i < 7; i++)
#pragma unroll
                for (int j = 0; j < 8; j++) acc[i][j] += a[i] * f[j];
        }
        __syncthreads();
    }
#pragma unroll
    for (int i = 0; i < 7; i++) {
        int c = ty + 16 * i;
        if (c >= KPG) continue;
#pragma unroll
        for (int j = 0; j < 8; j++) {
            int d = tx + 16 * j;
            atomicAdd(&out[(size_t)(g * KPG + c) * DD + d], acc[i][j]);
        }
    }
}

// ---------------- adj: per graph, assign_b^T [2000x100] @ tmp_b [2000x100] --
__global__ __launch_bounds__(256)
void adj_kernel(float* __restrict__ out) {   // out = d_out (adj part, pre-zeroed)
    const int g = blockIdx.y;
    const int split = blockIdx.x;      // 8 splits
    const int kbeg = split * (NPG / 8);
    const int kend = kbeg + (NPG / 8);
    const float* A = g_assign + (size_t)g * NPG * KPG;
    const float* T = g_tmp + (size_t)g * NPG * KPG;

    __shared__ float As[8][KPG];
    __shared__ float Ts[8][KPG];
    const int tx = threadIdx.x & 15;
    const int ty = threadIdx.x >> 4;

    float acc[7][7];
#pragma unroll
    for (int i = 0; i < 7; i++)
#pragma unroll
        for (int j = 0; j < 7; j++) acc[i][j] = 0.f;

    for (int k0 = kbeg; k0 < kend; k0 += 8) {
        int kc = min(8, kend - k0);
        for (int idx = threadIdx.x; idx < 8 * KPG; idx += 256) {
            int r = idx / KPG, c = idx % KPG;
            As[r][c] = (r < kc) ? A[(size_t)(k0 + r) * KPG + c] : 0.f;
            Ts[r][c] = (r < kc) ? T[(size_t)(k0 + r) * KPG + c] : 0.f;
        }
        __syncthreads();
#pragma unroll
        for (int k = 0; k < 8; k++) {
            float a[7], b[7];
#pragma unroll
            for (int i = 0; i < 7; i++) {
                int c = ty + 16 * i;
                a[i] = (c < KPG) ? As[k][c] : 0.f;
            }
#pragma unroll
            for (int j = 0; j < 7; j++) {
                int c = tx + 16 * j;
                b[j] = (c < KPG) ? Ts[k][c] : 0.f;
            }
#pragma unroll
            for (int i = 0; i < 7; i++)
#pragma unroll
                for (int j = 0; j < 7; j++) acc[i][j] += a[i] * b[j];
        }
        __syncthreads();
    }
#pragma unroll
    for (int i = 0; i < 7; i++) {
        int c1 = ty + 16 * i;
        if (c1 >= KPG) continue;
#pragma unroll
        for (int j = 0; j < 7; j++) {
            int c2 = tx + 16 * j;
            if (c2 >= KPG) continue;
            atomicAdd(&out[(size_t)(g * KPG + c1) * KK + (g * KPG + c2)], acc[i][j]);
        }
    }
}

// ---------------- launch ----------------------------------------------------
extern "C" void kernel_launch(void* const* d_in, const int* in_sizes, int n_in,
                              void* d_out, int out_size) {
    const float* h   = (const float*)d_in[0];
    const int*   src = (const int*)d_in[1];
    const int*   dst = (const int*)d_in[2];
    const float* W1f = (const float*)d_in[3];
    const float* b1f = (const float*)d_in[4];
    const float* W2f = (const float*)d_in[5];
    const float* b2f = (const float*)d_in[6];
    const float* W1p = (const float*)d_in[7];
    const float* b1p = (const float*)d_in[8];
    const float* W2p = (const float*)d_in[9];
    const float* b2p = (const float*)d_in[10];
    float* out = (float*)d_out;

    float *agg, *deg, *x, *t1, *feat, *x2, *logits, *assign, *tmp;
    cudaGetSymbolAddress((void**)&agg,    g_agg);
    cudaGetSymbolAddress((void**)&deg,    g_deg);
    cudaGetSymbolAddress((void**)&x,      g_x);
    cudaGetSymbolAddress((void**)&t1,     g_t1);
    cudaGetSymbolAddress((void**)&feat,   g_feat);
    cudaGetSymbolAddress((void**)&x2,     g_x2);
    cudaGetSymbolAddress((void**)&logits, g_logits);
    cudaGetSymbolAddress((void**)&assign, g_assign);
    cudaGetSymbolAddress((void**)&tmp,    g_tmp);

    // zero scratch + output
    zero_kernel<<<2048, 256>>>(agg, (size_t)NN * DD);
    zero_kernel<<<128, 256>>>(deg, (size_t)NN);
    zero_kernel<<<2048, 256>>>(tmp, (size_t)NN * KPG);
    zero_kernel<<<2048, 256>>>(out, (size_t)out_size);

    // edge aggregation (shared by both GIN branches)
    edge_agg_kernel<<<(EE * 32 + 255) / 256, 256>>>(h, src, dst);
    build_x_kernel<<<((size_t)NN * DD + 255) / 256, 256>>>(h);

    // feat branch: two 32000x128x128 GEMMs
    sgemm_kernel<<<dim3(250, 1, 1), 256>>>(x, W1f, b1f, t1,
                                           NN, DD, DD, DD, DD, DD, 0, 0, 0, 0);
    sgemm_kernel<<<dim3(250, 1, 1), 256>>>(t1, W2f, b2f, feat,
                                           NN, DD, DD, DD, DD, DD, 0, 0, 0, 0);

    // pool branch layer 1: 32000 x 1600 x 128
    sgemm_kernel<<<dim3(250, 13, 1), 256>>>(x, W1p, b1p, x2,
                                            NN, KK, DD, DD, KK, KK, 0, 0, 0, 0);

    // pool branch layer 2: per graph [2000,1600] @ [1600,100] -> compact logits
    sgemm_kernel<<<dim3(16, 1, NB), 256>>>(x2, W2p, b2p, logits,
                                           NPG, KPG, KK, KK, KK, KPG,
                                           (long)NPG * KK, (long)KPG,
                                           (long)NPG * KPG, (long)KPG);

    // masked softmax (compact in-block)
    softmax_kernel<<<(NN * 32 + 255) / 256, 256>>>();

    // tmp = scatter-add of assign over edges
    edge_tmp_kernel<<<(EE * 32 + 255) / 256, 256>>>(src, dst);

    // h_pool and adj (block-diagonal), atomic split-K into pre-zeroed d_out
    hpool_kernel<<<dim3(8, NB), 256>>>(out + ADJ_ELEMS);
    adj_kernel<<<dim3(8, NB), 256>>>(out);
}

// round 2
// speedup vs baseline: 1.2359x; 1.2359x over previous
#include <cuda_runtime.h>
#include <math.h>

// Problem constants
static constexpr int NN   = 32000;     // nodes
static constexpr int NB   = 16;        // graphs
static constexpr int NPG  = 2000;      // nodes per graph
static constexpr int KK   = 1600;      // clusters total
static constexpr int KPG  = 100;       // clusters per graph
static constexpr int DD   = 128;       // feature dim
static constexpr int EE   = 512000;    // edges
static constexpr int ADJ_ELEMS = KK * KK;

// ---------------- scratch (__device__ globals) ------------------------------
__device__ float g_x[(size_t)NN * DD];
__device__ float g_t1[(size_t)NN * DD];
__device__ float g_feat[(size_t)NN * DD];
__device__ float g_x2[(size_t)NN * KK];
__device__ float g_logits[(size_t)NN * KPG];
__device__ float g_assign[(size_t)NN * KPG];
__device__ float g_tmp[(size_t)NN * KPG];
__device__ int   g_degi[NN];
__device__ int   g_base[NN];
__device__ int   g_cursor[NN];
__device__ int   g_nbr[EE];

// ---------------- zero helpers ----------------------------------------------
__global__ void zero_f(float* __restrict__ p, size_t n) {
    size_t i = (size_t)blockIdx.x * blockDim.x + threadIdx.x;
    size_t st = (size_t)gridDim.x * blockDim.x;
    for (; i < n; i += st) p[i] = 0.f;
}
__global__ void zero_i(int* __restrict__ p, size_t n) {
    size_t i = (size_t)blockIdx.x * blockDim.x + threadIdx.x;
    size_t st = (size_t)gridDim.x * blockDim.x;
    for (; i < n; i += st) p[i] = 0;
}

// ---------------- CSR build --------------------------------------------------
__global__ void count_deg_kernel(const int* __restrict__ dst) {
    int e = blockIdx.x * blockDim.x + threadIdx.x;
    if (e < EE) atomicAdd(&g_degi[dst[e]], 1);
}

// single-block exclusive scan of g_degi -> g_base (and copy to g_cursor)
__global__ void scan_kernel() {
    __shared__ int buf[2][1024];
    __shared__ int carry_s;
    const int t = threadIdx.x;
    if (t == 0) carry_s = 0;
    __syncthreads();
    for (int c0 = 0; c0 < NN; c0 += 1024) {
        int v = (c0 + t < NN) ? g_degi[c0 + t] : 0;
        buf[0][t] = v;
        __syncthreads();
        int pp = 0;
        for (int off = 1; off < 1024; off <<= 1) {
            int x = buf[pp][t];
            int y = (t >= off) ? buf[pp][t - off] : 0;
            buf[pp ^ 1][t] = x + y;
            pp ^= 1;
            __syncthreads();
        }
        int incl = buf[pp][t];
        int carry = carry_s;
        __syncthreads();                 // everyone read old carry
        if (c0 + t < NN) {
            int excl = carry + incl - v;
            g_base[c0 + t]   = excl;
            g_cursor[c0 + t] = excl;
        }
        if (t == 1023) carry_s = carry + incl;
        __syncthreads();
    }
}

__global__ void fill_csr_kernel(const int* __restrict__ src,
                                const int* __restrict__ dst) {
    int e = blockIdx.x * blockDim.x + threadIdx.x;
    if (e >= EE) return;
    int p = atomicAdd(&g_cursor[dst[e]], 1);
    g_nbr[p] = src[e];
}

// ---------------- gather: x = h + mean_{s in N(n)} h[s] ---------------------
__global__ void gather_x_kernel(const float* __restrict__ h) {
    int n = (blockIdx.x * blockDim.x + threadIdx.x) >> 5;
    int lane = threadIdx.x & 31;
    if (n >= NN) return;
    int b = g_base[n];
    int dg = g_degi[n];
    float a0 = 0.f, a1 = 0.f, a2 = 0.f, a3 = 0.f;
    for (int j = 0; j < dg; j++) {
        const float* hr = h + (size_t)g_nbr[b + j] * DD;
        a0 += hr[lane];
        a1 += hr[lane + 32];
        a2 += hr[lane + 64];
        a3 += hr[lane + 96];
    }
    float inv = 1.f / fmaxf((float)dg, 1.f);
    const float* hn = h + (size_t)n * DD;
    float* xo = g_x + (size_t)n * DD;
    xo[lane]      = hn[lane]      + a0 * inv;
    xo[lane + 32] = hn[lane + 32] + a1 * inv;
    xo[lane + 64] = hn[lane + 64] + a2 * inv;
    xo[lane + 96] = hn[lane + 96] + a3 * inv;
}

// ---------------- gather: tmp[n] = sum_{s in N(n)} assign[s] ----------------
__global__ void gather_tmp_kernel() {
    int n = (blockIdx.x * blockDim.x + threadIdx.x) >> 5;
    int lane = threadIdx.x & 31;
    if (n >= NN) return;
    int b = g_base[n];
    int dg = g_degi[n];
    float a0 = 0.f, a1 = 0.f, a2 = 0.f, a3 = 0.f;
    for (int j = 0; j < dg; j++) {
        const float* ar = g_assign + (size_t)g_nbr[b + j] * KPG;
        a0 += ar[lane];
        a1 += ar[lane + 32];
        a2 += ar[lane + 64];
        if (lane < 4) a3 += ar[lane + 96];
    }
    float* tp = g_tmp + (size_t)n * KPG;
    tp[lane]      = a0;
    tp[lane + 32] = a1;
    tp[lane + 64] = a2;
    if (lane < 4) tp[lane + 96] = a3;
}

// ---------------- SGEMM: C = relu(A@B + bias) -------------------------------
// 128x128 tile, BK=8, 128 threads, 16x8 per thread, double-buffered smem.
__global__ __launch_bounds__(128)
void sgemm_kernel(const float* __restrict__ A, const float* __restrict__ B,
                  const float* __restrict__ bias, float* __restrict__ C,
                  int M, int N, int K, int lda, int ldb, int ldc,
                  long zsA, long zsB, long zsC, long zsBias) {
    A    += (size_t)blockIdx.z * zsA;
    B    += (size_t)blockIdx.z * zsB;
    C    += (size_t)blockIdx.z * zsC;
    bias += (size_t)blockIdx.z * zsBias;

    __shared__ float As[2][8][128];
    __shared__ float Bs[2][8][128];

    const int tid = threadIdx.x;
    const int bm = blockIdx.x * 128;
    const int bn = blockIdx.y * 128;
    const int rowBase = (tid >> 4) * 16;
    const int colBase = (tid & 15) * 8;

    const int aRow  = bm + tid;          // one A row per thread
    const int bRow  = tid >> 4;          // 0..7
    const int bColL = (tid & 15) * 8;    // 0..120
    const int bCol  = bn + bColL;
    const float* Aptr = A + (size_t)aRow * lda;
    const bool aOk = (aRow < M);
    const bool bOk0 = (bCol + 3 < N);
    const bool bOk1 = (bCol + 7 < N);

    float4 pa0, pa1, pb0, pb1;
    const float4 z4 = make_float4(0.f, 0.f, 0.f, 0.f);

    // prefetch tile 0
    {
        pa0 = aOk ? *(const float4*)(Aptr + 0) : z4;
        pa1 = aOk ? *(const float4*)(Aptr + 4) : z4;
        const float* bp = B + (size_t)bRow * ldb + bCol;
        pb0 = bOk0 ? *(const float4*)(bp) : z4;
        pb1 = bOk1 ? *(const float4*)(bp + 4) : z4;
    }
    // store tile 0
    As[0][0][tid] = pa0.x; As[0][1][tid] = pa0.y; As[0][2][tid] = pa0.z; As[0][3][tid] = pa0.w;
    As[0][4][tid] = pa1.x; As[0][5][tid] = pa1.y; As[0][6][tid] = pa1.z; As[0][7][tid] = pa1.w;
    *(float4*)&Bs[0][bRow][bColL]     = pb0;
    *(float4*)&Bs[0][bRow][bColL + 4] = pb1;
    __syncthreads();

    float acc[16][8];
#pragma unroll
    for (int i = 0; i < 16; i++)
#pragma unroll
        for (int j = 0; j < 8; j++) acc[i][j] = 0.f;

    const int nT = K >> 3;
    for (int t = 0; t < nT; t++) {
        const int cur = t & 1;
        if (t + 1 < nT) {
            const int k0 = (t + 1) * 8;
            pa0 = aOk ? *(const float4*)(Aptr + k0)     : z4;
            pa1 = aOk ? *(const float4*)(Aptr + k0 + 4) : z4;
            const float* bp = B + (size_t)(k0 + bRow) * ldb + bCol;
            pb0 = bOk0 ? *(const float4*)(bp)     : z4;
            pb1 = bOk1 ? *(const float4*)(bp + 4) : z4;
        }
#pragma unroll
        for (int k = 0; k < 8; k++) {
            float a[16], b[8];
            *(float4*)&a[0]  = *(const float4*)&As[cur][k][rowBase];
            *(float4*)&a[4]  = *(const float4*)&As[cur][k][rowBase + 4];
            *(float4*)&a[8]  = *(const float4*)&As[cur][k][rowBase + 8];
            *(float4*)&a[12] = *(const float4*)&As[cur][k][rowBase + 12];
            *(float4*)&b[0]  = *(const float4*)&Bs[cur][k][colBase];
            *(float4*)&b[4]  = *(const float4*)&Bs[cur][k][colBase + 4];
#pragma unroll
            for (int i = 0; i < 16; i++)
#pragma unroll
                for (int j = 0; j < 8; j++) acc[i][j] += a[i] * b[j];
        }
        if (t + 1 < nT) {
            const int nxt = (t + 1) & 1;
            As[nxt][0][tid] = pa0.x; As[nxt][1][tid] = pa0.y; As[nxt][2][tid] = pa0.z; As[nxt][3][tid] = pa0.w;
            As[nxt][4][tid] = pa1.x; As[nxt][5][tid] = pa1.y; As[nxt][6][tid] = pa1.z; As[nxt][7][tid] = pa1.w;
            *(float4*)&Bs[nxt][bRow][bColL]     = pb0;
            *(float4*)&Bs[nxt][bRow][bColL + 4] = pb1;
        }
        __syncthreads();
    }

#pragma unroll
    for (int i = 0; i < 16; i++) {
        int r = bm + rowBase + i;
        if (r >= M) continue;
        float* cp = C + (size_t)r * ldc + bn + colBase;
#pragma unroll
        for (int j = 0; j < 8; j++) {
            int c = bn + colBase + j;
            if (c < N) cp[j] = fmaxf(acc[i][j] + bias[c], 0.f);
        }
    }
}

// ---------------- per-node softmax over 100 compact logits ------------------
__global__ void softmax_kernel() {
    int node = (blockIdx.x * blockDim.x + threadIdx.x) >> 5;
    int lane = threadIdx.x & 31;
    if (node >= NN) return;
    const float* lp = g_logits + (size_t)node * KPG;
    float v[4];
    float mx = -1e30f;
#pragma unroll
    for (int i = 0; i < 4; i++) {
        int c = lane + 32 * i;
        v[i] = (c < KPG) ? lp[c] : -1e30f;
        mx = fmaxf(mx, v[i]);
    }
#pragma unroll
    for (int o = 16; o; o >>= 1) mx = fmaxf(mx, __shfl_xor_sync(0xFFFFFFFFu, mx, o));
    float sum = 0.f;
#pragma unroll
    for (int i = 0; i < 4; i++) {
        int c = lane + 32 * i;
        v[i] = (c < KPG) ? expf(v[i] - mx) : 0.f;
        sum += v[i];
    }
#pragma unroll
    for (int o = 16; o; o >>= 1) sum += __shfl_xor_sync(0xFFFFFFFFu, sum, o);
    float inv = 1.f / sum;
    float* ap = g_assign + (size_t)node * KPG;
#pragma unroll
    for (int i = 0; i < 4; i++) {
        int c = lane + 32 * i;
        if (c < KPG) ap[c] = v[i] * inv;
    }
}

// ---------------- h_pool: per graph, assign_b^T [2000x100] @ feat_b [2000x128]
__global__ __launch_bounds__(256)
void hpool_kernel(float* __restrict__ out) {   // out = d_out + ADJ_ELEMS
    const int g = blockIdx.y;
    const int split = blockIdx.x;      // 8 splits
    const int kbeg = split * (NPG / 8);
    const int kend = kbeg + (NPG / 8);
    const float* A = g_assign + (size_t)g * NPG * KPG;
    const float* F = g_feat + (size_t)g * NPG * DD;

    __shared__ float As[8][KPG];
    __shared__ float Fs[8][DD];
    const int tx = threadIdx.x & 15;
    const int ty = threadIdx.x >> 4;

    float acc[7][8];
#pragma unroll
    for (int i = 0; i < 7; i++)
#pragma unroll
        for (int j = 0; j < 8; j++) acc[i][j] = 0.f;

    for (int k0 = kbeg; k0 < kend; k0 += 8) {
        int kc = min(8, kend - k0);
        for (int idx = threadIdx.x; idx < 8 * KPG; idx += 256) {
            int r = idx / KPG, c = idx % KPG;
            As[r][c] = (r < kc) ? A[(size_t)(k0 + r) * KPG + c] : 0.f;
        }
        for (int idx = threadIdx.x; idx < 8 * DD; idx += 256) {
            int r = idx >> 7, c = idx & 127;
            Fs[r][c] = (r < kc) ? F[(size_t)(k0 + r) * DD + c] : 0.f;
        }
        __syncthreads();
#pragma unroll
        for (int k = 0; k < 8; k++) {
            float a[7], f[8];
#pragma unroll
            for (int i = 0; i < 7; i++) {
                int c = ty + 16 * i;
                a[i] = (c < KPG) ? As[k][c] : 0.f;
            }
#pragma unroll
            for (int j = 0; j < 8; j++) f[j] = Fs[k][tx + 16 * j];
#pragma unroll
            for (int i = 0; i < 7; i++)
#pragma unroll
                for (int j = 0; j < 8; j++) acc[i][j] += a[i] * f[j];
        }
        __syncthreads();
    }
#pragma unroll
    for (int i = 0; i < 7; i++) {
        int c = ty + 16 * i;
        if (c >= KPG) continue;
#pragma unroll
        for (int j = 0; j < 8; j++) {
            int d = tx + 16 * j;
            atomicAdd(&out[(size_t)(g * KPG + c) * DD + d], acc[i][j]);
        }
    }
}

// ---------------- adj: per graph, assign_b^T [2000x100] @ tmp_b [2000x100] --
__global__ __launch_bounds__(256)
void adj_kernel(float* __restrict__ out) {   // adj part of d_out (pre-zeroed)
    const int g = blockIdx.y;
    const int split = blockIdx.x;      // 8 splits
    const int kbeg = split * (NPG / 8);
    const int kend = kbeg + (NPG / 8);
    const float* A = g_assign + (size_t)g * NPG * KPG;
    const float* T = g_tmp + (size_t)g * NPG * KPG;

    __shared__ float As[8][KPG];
    __shared__ float Ts[8][KPG];
    const int tx = threadIdx.x & 15;
    const int ty = threadIdx.x >> 4;

    float acc[7][7];
#pragma unroll
    for (int i = 0; i < 7; i++)
#pragma unroll
        for (int j = 0; j < 7; j++) acc[i][j] = 0.f;

    for (int k0 = kbeg; k0 < kend; k0 += 8) {
        int kc = min(8, kend - k0);
        for (int idx = threadIdx.x; idx < 8 * KPG; idx += 256) {
            int r = idx / KPG, c = idx % KPG;
            As[r][c] = (r < kc) ? A[(size_t)(k0 + r) * KPG + c] : 0.f;
            Ts[r][c] = (r < kc) ? T[(size_t)(k0 + r) * KPG + c] : 0.f;
        }
        __syncthreads();
#pragma unroll
        for (int k = 0; k < 8; k++) {
            float a[7], b[7];
#pragma unroll
            for (int i = 0; i < 7; i++) {
                int c = ty + 16 * i;
                a[i] = (c < KPG) ? As[k][c] : 0.f;
            }
#pragma unroll
            for (int j = 0; j < 7; j++) {
                int c = tx + 16 * j;
                b[j] = (c < KPG) ? Ts[k][c] : 0.f;
            }
#pragma unroll
            for (int i = 0; i < 7; i++)
#pragma unroll
                for (int j = 0; j < 7; j++) acc[i][j] += a[i] * b[j];
        }
        __syncthreads();
    }
#pragma unroll
    for (int i = 0; i < 7; i++) {
        int c1 = ty + 16 * i;
        if (c1 >= KPG) continue;
#pragma unroll
        for (int j = 0; j < 7; j++) {
            int c2 = tx + 16 * j;
            if (c2 >= KPG) continue;
            atomicAdd(&out[(size_t)(g * KPG + c1) * KK + (g * KPG + c2)], acc[i][j]);
        }
    }
}

// ---------------- launch ----------------------------------------------------
extern "C" void kernel_launch(void* const* d_in, const int* in_sizes, int n_in,
                              void* d_out, int out_size) {
    const float* h   = (const float*)d_in[0];
    const int*   src = (const int*)d_in[1];
    const int*   dst = (const int*)d_in[2];
    const float* W1f = (const float*)d_in[3];
    const float* b1f = (const float*)d_in[4];
    const float* W2f = (const float*)d_in[5];
    const float* b2f = (const float*)d_in[6];
    const float* W1p = (const float*)d_in[7];
    const float* b1p = (const float*)d_in[8];
    const float* W2p = (const float*)d_in[9];
    const float* b2p = (const float*)d_in[10];
    float* out = (float*)d_out;

    float *x, *t1, *feat, *x2, *logits;
    int* degi;
    cudaGetSymbolAddress((void**)&x,      g_x);
    cudaGetSymbolAddress((void**)&t1,     g_t1);
    cudaGetSymbolAddress((void**)&feat,   g_feat);
    cudaGetSymbolAddress((void**)&x2,     g_x2);
    cudaGetSymbolAddress((void**)&logits, g_logits);
    cudaGetSymbolAddress((void**)&degi,   g_degi);

    // zero output + degree counters
    zero_f<<<1024, 256>>>(out, (size_t)out_size);
    zero_i<<<128, 256>>>(degi, (size_t)NN);

    // CSR build (dst-indexed neighbor lists)
    count_deg_kernel<<<(EE + 255) / 256, 256>>>(dst);
    scan_kernel<<<1, 1024>>>();
    fill_csr_kernel<<<(EE + 255) / 256, 256>>>(src, dst);

    // x = h + mean-aggregated neighbors (shared by both GIN branches)
    gather_x_kernel<<<(NN * 32 + 255) / 256, 256>>>(h);

    // feat branch: two 32000x128x128 GEMMs
    sgemm_kernel<<<dim3(250, 1, 1), 128>>>(x, W1f, b1f, t1,
                                           NN, DD, DD, DD, DD, DD, 0, 0, 0, 0);
    sgemm_kernel<<<dim3(250, 1, 1), 128>>>(t1, W2f, b2f, feat,
                                           NN, DD, DD, DD, DD, DD, 0, 0, 0, 0);

    // pool branch layer 1: 32000 x 1600 x 128
    sgemm_kernel<<<dim3(250, 13, 1), 128>>>(x, W1p, b1p, x2,
                                            NN, KK, DD, DD, KK, KK, 0, 0, 0, 0);

    // pool branch layer 2: per graph [2000,1600] @ [1600,100] -> compact logits
    sgemm_kernel<<<dim3(16, 1, NB), 128>>>(x2, W2p, b2p, logits,
                                           NPG, KPG, KK, KK, KK, KPG,
                                           (long)NPG * KK, (long)KPG,
                                           (long)NPG * KPG, (long)KPG);

    // masked softmax (compact in-block)
    softmax_kernel<<<(NN * 32 + 255) / 256, 256>>>();

    // tmp = gather-sum of assign over incoming edges (no atomics)
    gather_tmp_kernel<<<(NN * 32 + 255) / 256, 256>>>();

    // h_pool and adj (block-diagonal), atomic split-K into pre-zeroed d_out
    hpool_kernel<<<dim3(8, NB), 256>>>(out + ADJ_ELEMS);
    adj_kernel<<<dim3(8, NB), 256>>>(out);
}